// round 7
// baseline (speedup 1.0000x reference)
#include <cuda_runtime.h>
#include <cuda_bf16.h>
#include <stdint.h>

#define MAXC 4
#define ATOM_CAP 8388608

// Accumulator layout (doubles):
// per chain c (7): 0..2 poc_glob sum, 3..5 ref sum, 6 count
// then: rec pos sum (3), rec chain counts (MAXC),
//       pocket rp sum (3), pocket cross(rp,ref) sum (3)
#define ACC_CH(c,f) ((c)*7+(f))
#define ACC_RSUM  (MAXC*7)
#define ACC_RCNT  (MAXC*7+3)
#define ACC_PRP   (MAXC*7+3+MAXC)
#define ACC_PCR   (MAXC*7+6+MAXC)
#define ACC_N     (MAXC*7+9+MAXC)

__device__ double g_acc[ACC_N];   // statically zero; k_setup re-zeroes after use
// float params: bt[MAXC*3], origin[3], fm[3], tm[3]
#define PAR_BT 0
#define PAR_OR (MAXC*3)
#define PAR_FM (MAXC*3+3)
#define PAR_TM (MAXC*3+6)
#define PAR_N  (MAXC*3+9)
__device__ float g_par[PAR_N];
__device__ unsigned char g_chain[ATOM_CAP];  // atom -> chain+1; 0 = not rec.
                                             // Statically zero; rec entries rewritten
                                             // with IDENTICAL values every call.

__device__ __forceinline__ float warp_sum(float v) {
#pragma unroll
    for (int o = 16; o; o >>= 1) v += __shfl_down_sync(0xffffffffu, v, o);
    return v;
}
__device__ __forceinline__ int warp_sum_i(int v) {
#pragma unroll
    for (int o = 16; o; o >>= 1) v += __shfl_down_sync(0xffffffffu, v, o);
    return v;
}

// Fused 3-role kernel.
//  Role A [0, blkA):            rec gather -> chain map + global position sum
//  Role B [blkA, blkA+blkB):    pocket gathers -> per-chain poc_glob sums,
//                               global rp sum, global cross(rp, ref) sum
//  Role C [blkA+blkB, ..+blkC): coalesced streams -> per-chain rec counts,
//                               per-chain ref sums, per-chain pocket counts
// Slim register use per role + launch_bounds -> high occupancy for the
// latency-bound gather roles.
__global__ void __launch_bounds__(256, 6)
k_abc(const float* __restrict__ pos,
      const int* __restrict__ rec_idx,
      const int* __restrict__ cid,
      const float* __restrict__ refp,
      const int* __restrict__ pidx,
      const int* __restrict__ pcid,
      int n_rec, int n_poc, int blkA, int blkB, int blkC) {
    __shared__ float s[MAXC * 4 + 6];
    unsigned lane = threadIdx.x & 31u;

    if ((int)blockIdx.x < blkA) {
        // ---- Role A: rec gather, chain map, global position sum
        if (threadIdx.x < 3) s[threadIdx.x] = 0.f;
        __syncthreads();

        float px = 0.f, py = 0.f, pz = 0.f;
        int stride = blkA * blockDim.x;
#pragma unroll 2
        for (int i = blockIdx.x * blockDim.x + threadIdx.x; i < n_rec; i += stride) {
            int r = __ldg(rec_idx + i);
            float x = __ldg(pos + 3 * r);
            float y = __ldg(pos + 3 * r + 1);
            float z = __ldg(pos + 3 * r + 2);
            int c = __ldg(cid + i);
            if (r >= 0 && r < ATOM_CAP) g_chain[r] = (unsigned char)(c + 1);
            px += x; py += y; pz += z;
        }
        px = warp_sum(px); py = warp_sum(py); pz = warp_sum(pz);
        if (lane == 0) {
            atomicAdd(&s[0], px); atomicAdd(&s[1], py); atomicAdd(&s[2], pz);
        }
        __syncthreads();
        if (threadIdx.x < 3) {
            float v = s[threadIdx.x];
            if (v != 0.f) atomicAdd(&g_acc[ACC_RSUM + threadIdx.x], (double)v);
        }
    } else if ((int)blockIdx.x < blkA + blkB) {
        // ---- Role B: pocket gathers (BUG-faithful poc_glob = positions[pidx])
        for (int t = threadIdx.x; t < MAXC * 3 + 6; t += blockDim.x) s[t] = 0.f;
        __syncthreads();

        float a[MAXC][3];
#pragma unroll
        for (int c = 0; c < MAXC; ++c) { a[c][0] = 0.f; a[c][1] = 0.f; a[c][2] = 0.f; }
        float rpx = 0.f, rpy = 0.f, rpz = 0.f;
        float crx = 0.f, cry = 0.f, crz = 0.f;

        int bx = (int)blockIdx.x - blkA;
        int stride = blkB * blockDim.x;
#pragma unroll 2
        for (int j = bx * blockDim.x + threadIdx.x; j < n_poc; j += stride) {
            int p = __ldg(pidx + j);
            int c = __ldg(pcid + j);
            int r = __ldg(rec_idx + p);
            float gx = __ldg(pos + 3 * p), gy = __ldg(pos + 3 * p + 1), gz = __ldg(pos + 3 * p + 2);
            float rx = __ldg(refp + 3 * j), ry = __ldg(refp + 3 * j + 1), rz = __ldg(refp + 3 * j + 2);
            float wx = __ldg(pos + 3 * r), wy = __ldg(pos + 3 * r + 1), wz = __ldg(pos + 3 * r + 2);
            rpx += wx; rpy += wy; rpz += wz;
            crx += wy * rz - wz * ry;
            cry += wz * rx - wx * rz;
            crz += wx * ry - wy * rx;
#pragma unroll
            for (int cc = 0; cc < MAXC; ++cc) {
                if (c == cc) { a[cc][0] += gx; a[cc][1] += gy; a[cc][2] += gz; }
            }
        }
#pragma unroll
        for (int c = 0; c < MAXC; ++c) {
#pragma unroll
            for (int f = 0; f < 3; ++f) {
                float w = warp_sum(a[c][f]);
                if (lane == 0 && w != 0.f) atomicAdd(&s[c * 3 + f], w);
            }
        }
        rpx = warp_sum(rpx); rpy = warp_sum(rpy); rpz = warp_sum(rpz);
        crx = warp_sum(crx); cry = warp_sum(cry); crz = warp_sum(crz);
        if (lane == 0) {
            atomicAdd(&s[MAXC * 3 + 0], rpx); atomicAdd(&s[MAXC * 3 + 1], rpy);
            atomicAdd(&s[MAXC * 3 + 2], rpz); atomicAdd(&s[MAXC * 3 + 3], crx);
            atomicAdd(&s[MAXC * 3 + 4], cry); atomicAdd(&s[MAXC * 3 + 5], crz);
        }
        __syncthreads();
        for (int t = threadIdx.x; t < MAXC * 3 + 6; t += blockDim.x) {
            float v = s[t];
            if (v != 0.f) {
                int dst;
                if (t < MAXC * 3) dst = ACC_CH(t / 3, t % 3);      // poc_glob sums
                else if (t < MAXC * 3 + 3) dst = ACC_PRP + (t - MAXC * 3);
                else dst = ACC_PCR + (t - MAXC * 3 - 3);
                atomicAdd(&g_acc[dst], (double)v);
            }
        }
    } else {
        // ---- Role C: coalesced streams only.
        // rec chain counts (cid), per-chain ref sums + pocket counts (pcid, refp)
        for (int t = threadIdx.x; t < MAXC * 4 + MAXC; t += blockDim.x) s[t] = 0.f;
        __syncthreads();

        int rc[MAXC];          // rec counts
        float rs[MAXC][3];     // ref sums
        int pc[MAXC];          // pocket counts
#pragma unroll
        for (int c = 0; c < MAXC; ++c) {
            rc[c] = 0; pc[c] = 0; rs[c][0] = 0.f; rs[c][1] = 0.f; rs[c][2] = 0.f;
        }
        int bx = (int)blockIdx.x - blkA - blkB;
        int stride = blkC * blockDim.x;
#pragma unroll 2
        for (int i = bx * blockDim.x + threadIdx.x; i < n_rec; i += stride) {
            int c = __ldg(cid + i);
#pragma unroll
            for (int cc = 0; cc < MAXC; ++cc) if (c == cc) rc[cc]++;
        }
#pragma unroll 2
        for (int j = bx * blockDim.x + threadIdx.x; j < n_poc; j += stride) {
            int c = __ldg(pcid + j);
            float rx = __ldg(refp + 3 * j), ry = __ldg(refp + 3 * j + 1), rz = __ldg(refp + 3 * j + 2);
#pragma unroll
            for (int cc = 0; cc < MAXC; ++cc) {
                if (c == cc) { rs[cc][0] += rx; rs[cc][1] += ry; rs[cc][2] += rz; pc[cc]++; }
            }
        }
#pragma unroll
        for (int c = 0; c < MAXC; ++c) {
            int w = warp_sum_i(rc[c]);
            if (lane == 0 && w) atomicAdd(&s[c], (float)w);
#pragma unroll
            for (int f = 0; f < 3; ++f) {
                float wf = warp_sum(rs[c][f]);
                if (lane == 0 && wf != 0.f) atomicAdd(&s[MAXC + c * 3 + f], wf);
            }
            int w2 = warp_sum_i(pc[c]);
            if (lane == 0 && w2) atomicAdd(&s[MAXC * 4 + c], (float)w2);
        }
        __syncthreads();
        for (int t = threadIdx.x; t < MAXC * 4 + MAXC; t += blockDim.x) {
            float v = s[t];
            if (v != 0.f) {
                int dst;
                if (t < MAXC) dst = ACC_RCNT + t;                                // rec counts
                else if (t < MAXC * 4) dst = ACC_CH((t - MAXC) / 3, 3 + (t - MAXC) % 3);  // ref sums
                else dst = ACC_CH(t - MAXC * 4, 6);                              // pocket counts
                atomicAdd(&g_acc[dst], (double)v);
            }
        }
    }
}

// Tiny kernel: parallel-stage scalars, thread 0 computes bt, origin, F_mean,
// torque_mean analytically. Re-zeroes g_acc for the next replay.
__global__ void k_setup(const float* __restrict__ box,
                        const float* __restrict__ kptr,
                        int n_rec) {
    __shared__ double a[ACC_N];
    __shared__ float  sb[10];
    int t = threadIdx.x;
    if (t < ACC_N) a[t] = g_acc[t];
    if (t >= 64 && t < 73) sb[t - 64] = box[t - 64];
    if (t == 73) sb[9] = *kptr;
    __syncthreads();
    if (t < ACC_N) g_acc[t] = 0.0;
    if (t != 0) return;

    float r0x = sb[0], r0y = sb[1], r0z = sb[2];
    float r1x = sb[3], r1y = sb[4], r1z = sb[5];
    float r2x = sb[6], r2y = sb[7], r2z = sb[8];
    float i0 = 1.f / sb[0], i1 = 1.f / sb[4], i2 = 1.f / sb[8];
    float k2 = -2.f * sb[9];

    double otx = 0.0, oty = 0.0, otz = 0.0;
    double fbx = 0.0, fby = 0.0, fbz = 0.0;
    double tbx = 0.0, tby = 0.0, tbz = 0.0;
    double refx = 0.0, refy = 0.0, refz = 0.0;

#pragma unroll
    for (int c = 0; c < MAXC; ++c) {
        double cntd = a[ACC_CH(c, 6)];
        double inv = (cntd > 0.0) ? 1.0 / cntd : 0.0;
        float pcx = (float)(a[ACC_CH(c, 0)] * inv);
        float pcy = (float)(a[ACC_CH(c, 1)] * inv);
        float pcz = (float)(a[ACC_CH(c, 2)] * inv);
        double rsx = a[ACC_CH(c, 3)], rsy = a[ACC_CH(c, 4)], rsz = a[ACC_CH(c, 5)];
        refx += rsx; refy += rsy; refz += rsz;
        float rcx = (float)(rsx * inv), rcy = (float)(rsy * inv), rcz = (float)(rsz * inv);
        float dx = rcx - pcx, dy = rcy - pcy, dz = rcz - pcz;
        float s3 = rintf(dz * i2);
        dx -= s3 * r2x; dy -= s3 * r2y; dz -= s3 * r2z;
        float s2 = rintf(dy * i1);
        dx -= s2 * r1x; dy -= s2 * r1y; dz -= s2 * r1z;
        float s1 = rintf(dx * i0);
        float tx = s1 * r0x + s2 * r1x + s3 * r2x;
        float ty = s1 * r0y + s2 * r1y + s3 * r2y;
        float tz = s1 * r0z + s2 * r1z + s3 * r2z;
        g_par[PAR_BT + c * 3 + 0] = tx;
        g_par[PAR_BT + c * 3 + 1] = ty;
        g_par[PAR_BT + c * 3 + 2] = tz;
        double rc = a[ACC_RCNT + c];
        otx += rc * tx; oty += rc * ty; otz += rc * tz;
        fbx += cntd * tx; fby += cntd * ty; fbz += cntd * tz;
        tbx += (double)ty * rsz - (double)tz * rsy;
        tby += (double)tz * rsx - (double)tx * rsz;
        tbz += (double)tx * rsy - (double)ty * rsx;
    }
    double invR = 1.0 / (double)n_rec;
    double ox = (a[ACC_RSUM + 0] + otx) * invR;
    double oy = (a[ACC_RSUM + 1] + oty) * invR;
    double oz = (a[ACC_RSUM + 2] + otz) * invR;
    g_par[PAR_OR + 0] = (float)ox;
    g_par[PAR_OR + 1] = (float)oy;
    g_par[PAR_OR + 2] = (float)oz;

    double Fx = (double)k2 * (a[ACC_PRP + 0] - refx + fbx);
    double Fy = (double)k2 * (a[ACC_PRP + 1] - refy + fby);
    double Fz = (double)k2 * (a[ACC_PRP + 2] - refz + fbz);
    double Tx = -(double)k2 * (a[ACC_PCR + 0] + tbx);
    double Ty = -(double)k2 * (a[ACC_PCR + 1] + tby);
    double Tz = -(double)k2 * (a[ACC_PCR + 2] + tbz);
    Tx -= oy * Fz - oz * Fy;
    Ty -= oz * Fx - ox * Fz;
    Tz -= ox * Fy - oy * Fx;

    g_par[PAR_FM + 0] = (float)(Fx * invR);
    g_par[PAR_FM + 1] = (float)(Fy * invR);
    g_par[PAR_FM + 2] = (float)(Fz * invR);
    g_par[PAR_TM + 0] = (float)(Tx * invR);
    g_par[PAR_TM + 1] = (float)(Ty * invR);
    g_par[PAR_TM + 2] = (float)(Tz * invR);
}

// Pass C: coalesced output over ALL atoms, 4 atoms/thread, interleaved
// assignment; g_par staged in shared once per block.
#define OTPB 256
#define APT  4
#define TILE (OTPB * APT)
__global__ void k_out(const float* __restrict__ pos,
                      float* __restrict__ out, int n_atoms, int base) {
    __shared__ float sp[TILE * 3];
    __shared__ float so[TILE * 3];
    __shared__ float par[PAR_N];
    if (threadIdx.x < PAR_N) par[threadIdx.x] = g_par[threadIdx.x];

    long long a0 = (long long)blockIdx.x * TILE;
    bool full = (a0 + TILE <= (long long)n_atoms);

    if (full) {
        const float4* src = (const float4*)(pos + 3 * a0);
#pragma unroll
        for (int m = 0; m < 3; ++m)
            ((float4*)sp)[threadIdx.x + m * OTPB] = src[threadIdx.x + m * OTPB];
    } else {
        long long nfl = ((long long)n_atoms - a0) * 3;
        for (int t = threadIdx.x; t < nfl; t += OTPB)
            sp[t] = pos[3 * a0 + t];
    }
    __syncthreads();

    float fm0 = par[PAR_FM + 0], fm1 = par[PAR_FM + 1], fm2 = par[PAR_FM + 2];
    float tm0 = par[PAR_TM + 0], tm1 = par[PAR_TM + 1], tm2 = par[PAR_TM + 2];
    float or0 = par[PAR_OR + 0], or1 = par[PAR_OR + 1], or2 = par[PAR_OR + 2];

#pragma unroll
    for (int m = 0; m < APT; ++m) {
        int l = threadIdx.x + m * OTPB;
        long long a = a0 + l;
        float fx = 0.f, fy = 0.f, fz = 0.f;
        if (a < n_atoms) {
            int ch = g_chain[a];
            if (ch > 0) {
                int c = ch - 1;
                float cx = sp[3 * l + 0] + par[PAR_BT + c * 3 + 0] - or0;
                float cy = sp[3 * l + 1] + par[PAR_BT + c * 3 + 1] - or1;
                float cz = sp[3 * l + 2] + par[PAR_BT + c * 3 + 2] - or2;
                float inv = 1.f / (cx * cx + cy * cy + cz * cz);
                fx = fm0 + (tm1 * cz - tm2 * cy) * inv;
                fy = fm1 + (tm2 * cx - tm0 * cz) * inv;
                fz = fm2 + (tm0 * cy - tm1 * cx) * inv;
            }
        }
        so[3 * l + 0] = fx;
        so[3 * l + 1] = fy;
        so[3 * l + 2] = fz;
    }
    __syncthreads();

    if (full && ((base & 3) == 0)) {
        float4* dst = (float4*)(out + base + 3 * a0);
#pragma unroll
        for (int m = 0; m < 3; ++m)
            dst[threadIdx.x + m * OTPB] = ((const float4*)so)[threadIdx.x + m * OTPB];
    } else {
        long long nfl = ((long long)n_atoms - a0) * 3;
        if (nfl > (long long)TILE * 3) nfl = (long long)TILE * 3;
        for (int t = threadIdx.x; t < nfl; t += OTPB)
            out[(long long)base + 3 * a0 + t] = so[t];
    }
}

extern "C" void kernel_launch(void* const* d_in, const int* in_sizes, int n_in,
                              void* d_out, int out_size) {
    const float* positions = (const float*)d_in[0];
    const float* box       = (const float*)d_in[1];
    const float* ref_poc   = (const float*)d_in[2];
    const float* kptr      = (const float*)d_in[3];
    const int*   rec_idx   = (const int*)d_in[4];
    const int*   poc_idx   = (const int*)d_in[5];
    const int*   cid       = (const int*)d_in[6];
    const int*   pcid      = (const int*)d_in[7];

    int n_atoms = in_sizes[0] / 3;
    int n_rec   = in_sizes[4];
    int n_poc   = in_sizes[5];
    int base = out_size - 3 * n_atoms;
    if (base < 0) base = 0;

    const int TPB = 256;
    // One full wave at 6 blocks/SM on 148 SMs = 888 blocks, split by traffic.
    int blkA = 502, blkB = 314, blkC = 72;
    // Shrink for tiny inputs so grid-stride loops stay valid.
    int maxA = (n_rec + TPB - 1) / TPB; if (blkA > maxA) blkA = maxA;
    int maxB = (n_poc + TPB - 1) / TPB; if (blkB > maxB) blkB = maxB;
    int maxC = (n_rec + TPB - 1) / TPB; if (blkC > maxC) blkC = maxC;

    if (base > 0)  // zero any leading energy slot
        cudaMemsetAsync(d_out, 0, (size_t)base * sizeof(float));
    k_abc<<<blkA + blkB + blkC, TPB>>>(positions, rec_idx, cid, ref_poc,
                                       poc_idx, pcid, n_rec, n_poc,
                                       blkA, blkB, blkC);
    k_setup<<<1, 128>>>(box, kptr, n_rec);
    k_out<<<(n_atoms + TILE - 1) / TILE, OTPB>>>(positions, (float*)d_out, n_atoms, base);
}

// round 8
// speedup vs baseline: 1.1351x; 1.1351x over previous
#include <cuda_runtime.h>
#include <cuda_bf16.h>
#include <stdint.h>

#define MAXC 4
#define ATOM_CAP 8388608

// Accumulator layout (doubles):
// per chain c (7): 0..2 poc_glob sum, 3..5 ref sum, 6 count
// then: rec pos sum (3), rec chain counts (MAXC),
//       pocket rp sum (3), pocket cross(rp,ref) sum (3)
#define ACC_CH(c,f) ((c)*7+(f))
#define ACC_RSUM  (MAXC*7)
#define ACC_RCNT  (MAXC*7+3)
#define ACC_PRP   (MAXC*7+3+MAXC)
#define ACC_PCR   (MAXC*7+6+MAXC)
#define ACC_N     (MAXC*7+9+MAXC)

__device__ double g_acc[ACC_N];   // statically zero; k_setup re-zeroes after use
// float params: bt[MAXC*3], origin[3], fm[3], tm[3]
#define PAR_BT 0
#define PAR_OR (MAXC*3)
#define PAR_FM (MAXC*3+3)
#define PAR_TM (MAXC*3+6)
#define PAR_N  (MAXC*3+9)
__device__ float g_par[PAR_N];
__device__ unsigned char g_chain[ATOM_CAP];  // atom -> chain+1; 0 = not rec.
                                             // Statically zero; rec entries rewritten
                                             // with IDENTICAL values every call.

// Role striping: 12 slots per group; slots 0..6 -> A, 7..10 -> B, 11 -> C.
// CLC places consecutive bids on consecutive SMs, so striping guarantees every
// SM gets a 7:4:1 role mix (the contiguous split in R7 partitioned roles onto
// disjoint SM subsets and halved effective parallelism per role).
#define SLOTS   12
#define SLOT_A  7
#define SLOT_B  4
#define GROUPS  148
#define GRID    (SLOTS * GROUPS)          // 1776
#define NBLK_A  (SLOT_A * GROUPS)         // 1036
#define NBLK_B  (SLOT_B * GROUPS)         // 592
#define NBLK_C  (GROUPS)                  // 148

__device__ __forceinline__ float warp_sum(float v) {
#pragma unroll
    for (int o = 16; o; o >>= 1) v += __shfl_down_sync(0xffffffffu, v, o);
    return v;
}
__device__ __forceinline__ int warp_sum_i(int v) {
#pragma unroll
    for (int o = 16; o; o >>= 1) v += __shfl_down_sync(0xffffffffu, v, o);
    return v;
}

__global__ void __launch_bounds__(256, 6)
k_abc(const float* __restrict__ pos,
      const int* __restrict__ rec_idx,
      const int* __restrict__ cid,
      const float* __restrict__ refp,
      const int* __restrict__ pidx,
      const int* __restrict__ pcid,
      int n_rec, int n_poc) {
    __shared__ float s[MAXC * 4 + 6];
    unsigned lane = threadIdx.x & 31u;
    int slot = (int)blockIdx.x % SLOTS;
    int grp  = (int)blockIdx.x / SLOTS;

    if (slot < SLOT_A) {
        // ---- Role A: rec gather, chain map, global position sum
        int bx = grp * SLOT_A + slot;
        if (threadIdx.x < 3) s[threadIdx.x] = 0.f;
        __syncthreads();

        float px = 0.f, py = 0.f, pz = 0.f;
        int stride = NBLK_A * blockDim.x;
#pragma unroll 2
        for (int i = bx * blockDim.x + threadIdx.x; i < n_rec; i += stride) {
            int r = __ldg(rec_idx + i);
            float x = __ldg(pos + 3 * r);
            float y = __ldg(pos + 3 * r + 1);
            float z = __ldg(pos + 3 * r + 2);
            int c = __ldg(cid + i);
            if (r >= 0 && r < ATOM_CAP) g_chain[r] = (unsigned char)(c + 1);
            px += x; py += y; pz += z;
        }
        px = warp_sum(px); py = warp_sum(py); pz = warp_sum(pz);
        if (lane == 0) {
            atomicAdd(&s[0], px); atomicAdd(&s[1], py); atomicAdd(&s[2], pz);
        }
        __syncthreads();
        if (threadIdx.x < 3) {
            float v = s[threadIdx.x];
            if (v != 0.f) atomicAdd(&g_acc[ACC_RSUM + threadIdx.x], (double)v);
        }
    } else if (slot < SLOT_A + SLOT_B) {
        // ---- Role B: pocket gathers (BUG-faithful poc_glob = positions[pidx])
        int bx = grp * SLOT_B + (slot - SLOT_A);
        for (int t = threadIdx.x; t < MAXC * 3 + 6; t += blockDim.x) s[t] = 0.f;
        __syncthreads();

        float a[MAXC][3];
#pragma unroll
        for (int c = 0; c < MAXC; ++c) { a[c][0] = 0.f; a[c][1] = 0.f; a[c][2] = 0.f; }
        float rpx = 0.f, rpy = 0.f, rpz = 0.f;
        float crx = 0.f, cry = 0.f, crz = 0.f;

        int stride = NBLK_B * blockDim.x;
#pragma unroll 2
        for (int j = bx * blockDim.x + threadIdx.x; j < n_poc; j += stride) {
            int p = __ldg(pidx + j);
            int c = __ldg(pcid + j);
            int r = __ldg(rec_idx + p);
            float gx = __ldg(pos + 3 * p), gy = __ldg(pos + 3 * p + 1), gz = __ldg(pos + 3 * p + 2);
            float rx = __ldg(refp + 3 * j), ry = __ldg(refp + 3 * j + 1), rz = __ldg(refp + 3 * j + 2);
            float wx = __ldg(pos + 3 * r), wy = __ldg(pos + 3 * r + 1), wz = __ldg(pos + 3 * r + 2);
            rpx += wx; rpy += wy; rpz += wz;
            crx += wy * rz - wz * ry;
            cry += wz * rx - wx * rz;
            crz += wx * ry - wy * rx;
#pragma unroll
            for (int cc = 0; cc < MAXC; ++cc) {
                if (c == cc) { a[cc][0] += gx; a[cc][1] += gy; a[cc][2] += gz; }
            }
        }
#pragma unroll
        for (int c = 0; c < MAXC; ++c) {
#pragma unroll
            for (int f = 0; f < 3; ++f) {
                float w = warp_sum(a[c][f]);
                if (lane == 0 && w != 0.f) atomicAdd(&s[c * 3 + f], w);
            }
        }
        rpx = warp_sum(rpx); rpy = warp_sum(rpy); rpz = warp_sum(rpz);
        crx = warp_sum(crx); cry = warp_sum(cry); crz = warp_sum(crz);
        if (lane == 0) {
            atomicAdd(&s[MAXC * 3 + 0], rpx); atomicAdd(&s[MAXC * 3 + 1], rpy);
            atomicAdd(&s[MAXC * 3 + 2], rpz); atomicAdd(&s[MAXC * 3 + 3], crx);
            atomicAdd(&s[MAXC * 3 + 4], cry); atomicAdd(&s[MAXC * 3 + 5], crz);
        }
        __syncthreads();
        for (int t = threadIdx.x; t < MAXC * 3 + 6; t += blockDim.x) {
            float v = s[t];
            if (v != 0.f) {
                int dst;
                if (t < MAXC * 3) dst = ACC_CH(t / 3, t % 3);      // poc_glob sums
                else if (t < MAXC * 3 + 3) dst = ACC_PRP + (t - MAXC * 3);
                else dst = ACC_PCR + (t - MAXC * 3 - 3);
                atomicAdd(&g_acc[dst], (double)v);
            }
        }
    } else {
        // ---- Role C: coalesced streams only.
        // rec chain counts (cid), per-chain ref sums + pocket counts (pcid, refp)
        int bx = grp;
        for (int t = threadIdx.x; t < MAXC * 4 + MAXC; t += blockDim.x) s[t] = 0.f;
        __syncthreads();

        int rc[MAXC];
        float rs[MAXC][3];
        int pc[MAXC];
#pragma unroll
        for (int c = 0; c < MAXC; ++c) {
            rc[c] = 0; pc[c] = 0; rs[c][0] = 0.f; rs[c][1] = 0.f; rs[c][2] = 0.f;
        }
        int stride = NBLK_C * blockDim.x;
#pragma unroll 2
        for (int i = bx * blockDim.x + threadIdx.x; i < n_rec; i += stride) {
            int c = __ldg(cid + i);
#pragma unroll
            for (int cc = 0; cc < MAXC; ++cc) if (c == cc) rc[cc]++;
        }
#pragma unroll 2
        for (int j = bx * blockDim.x + threadIdx.x; j < n_poc; j += stride) {
            int c = __ldg(pcid + j);
            float rx = __ldg(refp + 3 * j), ry = __ldg(refp + 3 * j + 1), rz = __ldg(refp + 3 * j + 2);
#pragma unroll
            for (int cc = 0; cc < MAXC; ++cc) {
                if (c == cc) { rs[cc][0] += rx; rs[cc][1] += ry; rs[cc][2] += rz; pc[cc]++; }
            }
        }
#pragma unroll
        for (int c = 0; c < MAXC; ++c) {
            int w = warp_sum_i(rc[c]);
            if (lane == 0 && w) atomicAdd(&s[c], (float)w);
#pragma unroll
            for (int f = 0; f < 3; ++f) {
                float wf = warp_sum(rs[c][f]);
                if (lane == 0 && wf != 0.f) atomicAdd(&s[MAXC + c * 3 + f], wf);
            }
            int w2 = warp_sum_i(pc[c]);
            if (lane == 0 && w2) atomicAdd(&s[MAXC * 4 + c], (float)w2);
        }
        __syncthreads();
        for (int t = threadIdx.x; t < MAXC * 4 + MAXC; t += blockDim.x) {
            float v = s[t];
            if (v != 0.f) {
                int dst;
                if (t < MAXC) dst = ACC_RCNT + t;
                else if (t < MAXC * 4) dst = ACC_CH((t - MAXC) / 3, 3 + (t - MAXC) % 3);
                else dst = ACC_CH(t - MAXC * 4, 6);
                atomicAdd(&g_acc[dst], (double)v);
            }
        }
    }
}

// Tiny kernel: parallel-stage scalars, thread 0 computes bt, origin, F_mean,
// torque_mean analytically. Re-zeroes g_acc for the next replay.
__global__ void k_setup(const float* __restrict__ box,
                        const float* __restrict__ kptr,
                        int n_rec) {
    __shared__ double a[ACC_N];
    __shared__ float  sb[10];
    int t = threadIdx.x;
    if (t < ACC_N) a[t] = g_acc[t];
    if (t >= 64 && t < 73) sb[t - 64] = box[t - 64];
    if (t == 73) sb[9] = *kptr;
    __syncthreads();
    if (t < ACC_N) g_acc[t] = 0.0;
    if (t != 0) return;

    float r0x = sb[0], r0y = sb[1], r0z = sb[2];
    float r1x = sb[3], r1y = sb[4], r1z = sb[5];
    float r2x = sb[6], r2y = sb[7], r2z = sb[8];
    float i0 = 1.f / sb[0], i1 = 1.f / sb[4], i2 = 1.f / sb[8];
    float k2 = -2.f * sb[9];

    double otx = 0.0, oty = 0.0, otz = 0.0;
    double fbx = 0.0, fby = 0.0, fbz = 0.0;
    double tbx = 0.0, tby = 0.0, tbz = 0.0;
    double refx = 0.0, refy = 0.0, refz = 0.0;

#pragma unroll
    for (int c = 0; c < MAXC; ++c) {
        double cntd = a[ACC_CH(c, 6)];
        double inv = (cntd > 0.0) ? 1.0 / cntd : 0.0;
        float pcx = (float)(a[ACC_CH(c, 0)] * inv);
        float pcy = (float)(a[ACC_CH(c, 1)] * inv);
        float pcz = (float)(a[ACC_CH(c, 2)] * inv);
        double rsx = a[ACC_CH(c, 3)], rsy = a[ACC_CH(c, 4)], rsz = a[ACC_CH(c, 5)];
        refx += rsx; refy += rsy; refz += rsz;
        float rcx = (float)(rsx * inv), rcy = (float)(rsy * inv), rcz = (float)(rsz * inv);
        float dx = rcx - pcx, dy = rcy - pcy, dz = rcz - pcz;
        float s3 = rintf(dz * i2);
        dx -= s3 * r2x; dy -= s3 * r2y; dz -= s3 * r2z;
        float s2 = rintf(dy * i1);
        dx -= s2 * r1x; dy -= s2 * r1y; dz -= s2 * r1z;
        float s1 = rintf(dx * i0);
        float tx = s1 * r0x + s2 * r1x + s3 * r2x;
        float ty = s1 * r0y + s2 * r1y + s3 * r2y;
        float tz = s1 * r0z + s2 * r1z + s3 * r2z;
        g_par[PAR_BT + c * 3 + 0] = tx;
        g_par[PAR_BT + c * 3 + 1] = ty;
        g_par[PAR_BT + c * 3 + 2] = tz;
        double rc = a[ACC_RCNT + c];
        otx += rc * tx; oty += rc * ty; otz += rc * tz;
        fbx += cntd * tx; fby += cntd * ty; fbz += cntd * tz;
        tbx += (double)ty * rsz - (double)tz * rsy;
        tby += (double)tz * rsx - (double)tx * rsz;
        tbz += (double)tx * rsy - (double)ty * rsx;
    }
    double invR = 1.0 / (double)n_rec;
    double ox = (a[ACC_RSUM + 0] + otx) * invR;
    double oy = (a[ACC_RSUM + 1] + oty) * invR;
    double oz = (a[ACC_RSUM + 2] + otz) * invR;
    g_par[PAR_OR + 0] = (float)ox;
    g_par[PAR_OR + 1] = (float)oy;
    g_par[PAR_OR + 2] = (float)oz;

    double Fx = (double)k2 * (a[ACC_PRP + 0] - refx + fbx);
    double Fy = (double)k2 * (a[ACC_PRP + 1] - refy + fby);
    double Fz = (double)k2 * (a[ACC_PRP + 2] - refz + fbz);
    double Tx = -(double)k2 * (a[ACC_PCR + 0] + tbx);
    double Ty = -(double)k2 * (a[ACC_PCR + 1] + tby);
    double Tz = -(double)k2 * (a[ACC_PCR + 2] + tbz);
    Tx -= oy * Fz - oz * Fy;
    Ty -= oz * Fx - ox * Fz;
    Tz -= ox * Fy - oy * Fx;

    g_par[PAR_FM + 0] = (float)(Fx * invR);
    g_par[PAR_FM + 1] = (float)(Fy * invR);
    g_par[PAR_FM + 2] = (float)(Fz * invR);
    g_par[PAR_TM + 0] = (float)(Tx * invR);
    g_par[PAR_TM + 1] = (float)(Ty * invR);
    g_par[PAR_TM + 2] = (float)(Tz * invR);
}

// Pass C: coalesced output over ALL atoms, 4 atoms/thread, interleaved
// assignment; g_par staged in shared once per block.
#define OTPB 256
#define APT  4
#define TILE (OTPB * APT)
__global__ void k_out(const float* __restrict__ pos,
                      float* __restrict__ out, int n_atoms, int base) {
    __shared__ float sp[TILE * 3];
    __shared__ float so[TILE * 3];
    __shared__ float par[PAR_N];
    if (threadIdx.x < PAR_N) par[threadIdx.x] = g_par[threadIdx.x];

    long long a0 = (long long)blockIdx.x * TILE;
    bool full = (a0 + TILE <= (long long)n_atoms);

    if (full) {
        const float4* src = (const float4*)(pos + 3 * a0);
#pragma unroll
        for (int m = 0; m < 3; ++m)
            ((float4*)sp)[threadIdx.x + m * OTPB] = src[threadIdx.x + m * OTPB];
    } else {
        long long nfl = ((long long)n_atoms - a0) * 3;
        for (int t = threadIdx.x; t < nfl; t += OTPB)
            sp[t] = pos[3 * a0 + t];
    }
    __syncthreads();

    float fm0 = par[PAR_FM + 0], fm1 = par[PAR_FM + 1], fm2 = par[PAR_FM + 2];
    float tm0 = par[PAR_TM + 0], tm1 = par[PAR_TM + 1], tm2 = par[PAR_TM + 2];
    float or0 = par[PAR_OR + 0], or1 = par[PAR_OR + 1], or2 = par[PAR_OR + 2];

#pragma unroll
    for (int m = 0; m < APT; ++m) {
        int l = threadIdx.x + m * OTPB;
        long long a = a0 + l;
        float fx = 0.f, fy = 0.f, fz = 0.f;
        if (a < n_atoms) {
            int ch = g_chain[a];
            if (ch > 0) {
                int c = ch - 1;
                float cx = sp[3 * l + 0] + par[PAR_BT + c * 3 + 0] - or0;
                float cy = sp[3 * l + 1] + par[PAR_BT + c * 3 + 1] - or1;
                float cz = sp[3 * l + 2] + par[PAR_BT + c * 3 + 2] - or2;
                float inv = 1.f / (cx * cx + cy * cy + cz * cz);
                fx = fm0 + (tm1 * cz - tm2 * cy) * inv;
                fy = fm1 + (tm2 * cx - tm0 * cz) * inv;
                fz = fm2 + (tm0 * cy - tm1 * cx) * inv;
            }
        }
        so[3 * l + 0] = fx;
        so[3 * l + 1] = fy;
        so[3 * l + 2] = fz;
    }
    __syncthreads();

    if (full && ((base & 3) == 0)) {
        float4* dst = (float4*)(out + base + 3 * a0);
#pragma unroll
        for (int m = 0; m < 3; ++m)
            dst[threadIdx.x + m * OTPB] = ((const float4*)so)[threadIdx.x + m * OTPB];
    } else {
        long long nfl = ((long long)n_atoms - a0) * 3;
        if (nfl > (long long)TILE * 3) nfl = (long long)TILE * 3;
        for (int t = threadIdx.x; t < nfl; t += OTPB)
            out[(long long)base + 3 * a0 + t] = so[t];
    }
}

extern "C" void kernel_launch(void* const* d_in, const int* in_sizes, int n_in,
                              void* d_out, int out_size) {
    const float* positions = (const float*)d_in[0];
    const float* box       = (const float*)d_in[1];
    const float* ref_poc   = (const float*)d_in[2];
    const float* kptr      = (const float*)d_in[3];
    const int*   rec_idx   = (const int*)d_in[4];
    const int*   poc_idx   = (const int*)d_in[5];
    const int*   cid       = (const int*)d_in[6];
    const int*   pcid      = (const int*)d_in[7];

    int n_atoms = in_sizes[0] / 3;
    int n_rec   = in_sizes[4];
    int n_poc   = in_sizes[5];
    int base = out_size - 3 * n_atoms;
    if (base < 0) base = 0;

    if (base > 0)  // zero any leading energy slot
        cudaMemsetAsync(d_out, 0, (size_t)base * sizeof(float));
    k_abc<<<GRID, 256>>>(positions, rec_idx, cid, ref_poc, poc_idx, pcid,
                         n_rec, n_poc);
    k_setup<<<1, 128>>>(box, kptr, n_rec);
    k_out<<<(n_atoms + TILE - 1) / TILE, OTPB>>>(positions, (float*)d_out, n_atoms, base);
}

// round 9
// speedup vs baseline: 1.4791x; 1.3031x over previous
#include <cuda_runtime.h>
#include <cuda_bf16.h>
#include <stdint.h>

#define MAXC 4
#define ATOM_CAP 8388608

// Accumulator layout (doubles):
// per chain c (7): 0..2 poc_glob sum, 3..5 ref sum, 6 count
// then: rec pos sum (3), rec chain counts (MAXC),
//       pocket rp sum (3), pocket cross(rp,ref) sum (3)
#define ACC_CH(c,f) ((c)*7+(f))
#define ACC_RSUM  (MAXC*7)
#define ACC_RCNT  (MAXC*7+3)
#define ACC_PRP   (MAXC*7+3+MAXC)
#define ACC_PCR   (MAXC*7+6+MAXC)
#define ACC_N     (MAXC*7+9+MAXC)

__device__ double g_acc[ACC_N];   // statically zero; k_setup re-zeroes after use
// float params: bt[MAXC*3], origin[3], fm[3], tm[3]
#define PAR_BT 0
#define PAR_OR (MAXC*3)
#define PAR_FM (MAXC*3+3)
#define PAR_TM (MAXC*3+6)
#define PAR_N  (MAXC*3+9)
__device__ float g_par[PAR_N];
__device__ unsigned char g_chain[ATOM_CAP];  // atom -> chain+1; 0 = not rec.
                                             // Statically zero; rec entries rewritten
                                             // with IDENTICAL values every call.

__device__ __forceinline__ float warp_sum(float v) {
#pragma unroll
    for (int o = 16; o; o >>= 1) v += __shfl_down_sync(0xffffffffu, v, o);
    return v;
}
__device__ __forceinline__ int warp_sum_i(int v) {
#pragma unroll
    for (int o = 16; o; o >>= 1) v += __shfl_down_sync(0xffffffffu, v, o);
    return v;
}

// Fused pass A+B (R6 structure, 2-wide items for MLP).
// Blocks [0, blkA): rec work. Blocks [blkA, blkA+blkB): pocket work.
// Grid spans multiple waves, so the contiguous role split still lands every
// role on all SMs (R7's one-wave contiguous split was the failure mode).
// No launch_bounds: ptxas needs register headroom to batch gather loads
// (R8 showed regs 64->40 cost more MLP than the occupancy gain returned).
__global__ void k_ab(const float* __restrict__ pos,
                     const int* __restrict__ rec_idx,
                     const int* __restrict__ cid,
                     const float* __restrict__ refp,
                     const int* __restrict__ pidx,
                     const int* __restrict__ pcid,
                     int n_rec, int n_poc, int blkA, int blkB) {
    __shared__ float s[MAXC * 7 + 6];
    unsigned lane = threadIdx.x & 31u;

    if ((int)blockIdx.x < blkA) {
        // ---- Role A: rec gather (2 items/iter), chain map, position sum,
        //      per-chain counts
        if (threadIdx.x < 3 + MAXC) s[threadIdx.x] = 0.f;
        __syncthreads();

        float px = 0.f, py = 0.f, pz = 0.f;
        int cnt[MAXC];
#pragma unroll
        for (int c = 0; c < MAXC; ++c) cnt[c] = 0;

        int npair = (n_rec + 1) >> 1;
        int stride = blkA * blockDim.x;
        for (int q = blockIdx.x * blockDim.x + threadIdx.x; q < npair; q += stride) {
            int i0 = 2 * q;
            if (i0 + 1 < n_rec) {
                int2 rr = __ldg((const int2*)(rec_idx) + q);
                int2 cc2 = __ldg((const int2*)(cid) + q);
                float x0 = __ldg(pos + 3 * rr.x), y0 = __ldg(pos + 3 * rr.x + 1), z0 = __ldg(pos + 3 * rr.x + 2);
                float x1 = __ldg(pos + 3 * rr.y), y1 = __ldg(pos + 3 * rr.y + 1), z1 = __ldg(pos + 3 * rr.y + 2);
                if (rr.x >= 0 && rr.x < ATOM_CAP) g_chain[rr.x] = (unsigned char)(cc2.x + 1);
                if (rr.y >= 0 && rr.y < ATOM_CAP) g_chain[rr.y] = (unsigned char)(cc2.y + 1);
                px += x0 + x1; py += y0 + y1; pz += z0 + z1;
#pragma unroll
                for (int c = 0; c < MAXC; ++c) {
                    if (cc2.x == c) cnt[c]++;
                    if (cc2.y == c) cnt[c]++;
                }
            } else {
                int r = __ldg(rec_idx + i0);
                int c = __ldg(cid + i0);
                px += __ldg(pos + 3 * r);
                py += __ldg(pos + 3 * r + 1);
                pz += __ldg(pos + 3 * r + 2);
                if (r >= 0 && r < ATOM_CAP) g_chain[r] = (unsigned char)(c + 1);
#pragma unroll
                for (int c2 = 0; c2 < MAXC; ++c2) if (c == c2) cnt[c2]++;
            }
        }
        px = warp_sum(px); py = warp_sum(py); pz = warp_sum(pz);
        if (lane == 0) {
            atomicAdd(&s[0], px); atomicAdd(&s[1], py); atomicAdd(&s[2], pz);
        }
#pragma unroll
        for (int c = 0; c < MAXC; ++c) {
            int w = warp_sum_i(cnt[c]);
            if (lane == 0 && w) atomicAdd(&s[3 + c], (float)w);
        }
        __syncthreads();
        if (threadIdx.x < 3) {
            float v = s[threadIdx.x];
            if (v != 0.f) atomicAdd(&g_acc[ACC_RSUM + threadIdx.x], (double)v);
        }
        if (threadIdx.x >= 3 && threadIdx.x < 3 + MAXC) {
            float v = s[threadIdx.x];
            if (v != 0.f) atomicAdd(&g_acc[ACC_RCNT + threadIdx.x - 3], (double)v);
        }
    } else {
        // ---- Role B: pocket sums, 2 items/iter (BUG-faithful
        //      poc_glob = positions[pidx])
        for (int t = threadIdx.x; t < MAXC * 7 + 6; t += blockDim.x) s[t] = 0.f;
        __syncthreads();

        float a[MAXC][6];
        int   an[MAXC];
#pragma unroll
        for (int c = 0; c < MAXC; ++c) {
#pragma unroll
            for (int f = 0; f < 6; ++f) a[c][f] = 0.f;
            an[c] = 0;
        }
        float rpx = 0.f, rpy = 0.f, rpz = 0.f;
        float crx = 0.f, cry = 0.f, crz = 0.f;

        int bx = (int)blockIdx.x - blkA;
        int npair = (n_poc + 1) >> 1;
        int stride = blkB * blockDim.x;
        for (int q = bx * blockDim.x + threadIdx.x; q < npair; q += stride) {
            int j0 = 2 * q;
            if (j0 + 1 < n_poc) {
                int2 pp = __ldg((const int2*)(pidx) + q);
                int2 cc2 = __ldg((const int2*)(pcid) + q);
                int r0 = __ldg(rec_idx + pp.x);
                int r1 = __ldg(rec_idx + pp.y);
                float gx0 = __ldg(pos + 3 * pp.x), gy0 = __ldg(pos + 3 * pp.x + 1), gz0 = __ldg(pos + 3 * pp.x + 2);
                float gx1 = __ldg(pos + 3 * pp.y), gy1 = __ldg(pos + 3 * pp.y + 1), gz1 = __ldg(pos + 3 * pp.y + 2);
                float rx0 = __ldg(refp + 3 * j0),     ry0 = __ldg(refp + 3 * j0 + 1), rz0 = __ldg(refp + 3 * j0 + 2);
                float rx1 = __ldg(refp + 3 * j0 + 3), ry1 = __ldg(refp + 3 * j0 + 4), rz1 = __ldg(refp + 3 * j0 + 5);
                float wx0 = __ldg(pos + 3 * r0), wy0 = __ldg(pos + 3 * r0 + 1), wz0 = __ldg(pos + 3 * r0 + 2);
                float wx1 = __ldg(pos + 3 * r1), wy1 = __ldg(pos + 3 * r1 + 1), wz1 = __ldg(pos + 3 * r1 + 2);
                rpx += wx0 + wx1; rpy += wy0 + wy1; rpz += wz0 + wz1;
                crx += wy0 * rz0 - wz0 * ry0 + wy1 * rz1 - wz1 * ry1;
                cry += wz0 * rx0 - wx0 * rz0 + wz1 * rx1 - wx1 * rz1;
                crz += wx0 * ry0 - wy0 * rx0 + wx1 * ry1 - wy1 * rx1;
#pragma unroll
                for (int c = 0; c < MAXC; ++c) {
                    if (cc2.x == c) {
                        a[c][0] += gx0; a[c][1] += gy0; a[c][2] += gz0;
                        a[c][3] += rx0; a[c][4] += ry0; a[c][5] += rz0;
                        an[c]++;
                    }
                    if (cc2.y == c) {
                        a[c][0] += gx1; a[c][1] += gy1; a[c][2] += gz1;
                        a[c][3] += rx1; a[c][4] += ry1; a[c][5] += rz1;
                        an[c]++;
                    }
                }
            } else {
                int p = __ldg(pidx + j0);
                int c = __ldg(pcid + j0);
                int r = __ldg(rec_idx + p);
                float gx = __ldg(pos + 3 * p), gy = __ldg(pos + 3 * p + 1), gz = __ldg(pos + 3 * p + 2);
                float rx = __ldg(refp + 3 * j0), ry = __ldg(refp + 3 * j0 + 1), rz = __ldg(refp + 3 * j0 + 2);
                float wx = __ldg(pos + 3 * r), wy = __ldg(pos + 3 * r + 1), wz = __ldg(pos + 3 * r + 2);
                rpx += wx; rpy += wy; rpz += wz;
                crx += wy * rz - wz * ry;
                cry += wz * rx - wx * rz;
                crz += wx * ry - wy * rx;
#pragma unroll
                for (int c2 = 0; c2 < MAXC; ++c2) {
                    if (c == c2) {
                        a[c2][0] += gx; a[c2][1] += gy; a[c2][2] += gz;
                        a[c2][3] += rx; a[c2][4] += ry; a[c2][5] += rz;
                        an[c2]++;
                    }
                }
            }
        }
#pragma unroll
        for (int c = 0; c < MAXC; ++c) {
#pragma unroll
            for (int f = 0; f < 6; ++f) {
                float w = warp_sum(a[c][f]);
                if (lane == 0 && w != 0.f) atomicAdd(&s[c * 7 + f], w);
            }
            int w = warp_sum_i(an[c]);
            if (lane == 0 && w) atomicAdd(&s[c * 7 + 6], (float)w);
        }
        rpx = warp_sum(rpx); rpy = warp_sum(rpy); rpz = warp_sum(rpz);
        crx = warp_sum(crx); cry = warp_sum(cry); crz = warp_sum(crz);
        if (lane == 0) {
            atomicAdd(&s[MAXC * 7 + 0], rpx); atomicAdd(&s[MAXC * 7 + 1], rpy);
            atomicAdd(&s[MAXC * 7 + 2], rpz); atomicAdd(&s[MAXC * 7 + 3], crx);
            atomicAdd(&s[MAXC * 7 + 4], cry); atomicAdd(&s[MAXC * 7 + 5], crz);
        }
        __syncthreads();
        for (int t = threadIdx.x; t < MAXC * 7 + 6; t += blockDim.x) {
            float v = s[t];
            if (v != 0.f) {
                int dst = (t < MAXC * 7) ? t
                         : (t < MAXC * 7 + 3 ? ACC_PRP + (t - MAXC * 7)
                                             : ACC_PCR + (t - MAXC * 7 - 3));
                atomicAdd(&g_acc[dst], (double)v);
            }
        }
    }
}

// Tiny kernel: parallel-stage scalars, thread 0 computes bt, origin, F_mean,
// torque_mean analytically. Re-zeroes g_acc for the next replay.
__global__ void k_setup(const float* __restrict__ box,
                        const float* __restrict__ kptr,
                        int n_rec) {
    __shared__ double a[ACC_N];
    __shared__ float  sb[10];
    int t = threadIdx.x;
    if (t < ACC_N) a[t] = g_acc[t];
    if (t >= 64 && t < 73) sb[t - 64] = box[t - 64];
    if (t == 73) sb[9] = *kptr;
    __syncthreads();
    if (t < ACC_N) g_acc[t] = 0.0;
    if (t != 0) return;

    float r0x = sb[0], r0y = sb[1], r0z = sb[2];
    float r1x = sb[3], r1y = sb[4], r1z = sb[5];
    float r2x = sb[6], r2y = sb[7], r2z = sb[8];
    float i0 = 1.f / sb[0], i1 = 1.f / sb[4], i2 = 1.f / sb[8];
    float k2 = -2.f * sb[9];

    double otx = 0.0, oty = 0.0, otz = 0.0;
    double fbx = 0.0, fby = 0.0, fbz = 0.0;
    double tbx = 0.0, tby = 0.0, tbz = 0.0;
    double refx = 0.0, refy = 0.0, refz = 0.0;

#pragma unroll
    for (int c = 0; c < MAXC; ++c) {
        double cntd = a[ACC_CH(c, 6)];
        double inv = (cntd > 0.0) ? 1.0 / cntd : 0.0;
        float pcx = (float)(a[ACC_CH(c, 0)] * inv);
        float pcy = (float)(a[ACC_CH(c, 1)] * inv);
        float pcz = (float)(a[ACC_CH(c, 2)] * inv);
        double rsx = a[ACC_CH(c, 3)], rsy = a[ACC_CH(c, 4)], rsz = a[ACC_CH(c, 5)];
        refx += rsx; refy += rsy; refz += rsz;
        float rcx = (float)(rsx * inv), rcy = (float)(rsy * inv), rcz = (float)(rsz * inv);
        float dx = rcx - pcx, dy = rcy - pcy, dz = rcz - pcz;
        float s3 = rintf(dz * i2);
        dx -= s3 * r2x; dy -= s3 * r2y; dz -= s3 * r2z;
        float s2 = rintf(dy * i1);
        dx -= s2 * r1x; dy -= s2 * r1y; dz -= s2 * r1z;
        float s1 = rintf(dx * i0);
        float tx = s1 * r0x + s2 * r1x + s3 * r2x;
        float ty = s1 * r0y + s2 * r1y + s3 * r2y;
        float tz = s1 * r0z + s2 * r1z + s3 * r2z;
        g_par[PAR_BT + c * 3 + 0] = tx;
        g_par[PAR_BT + c * 3 + 1] = ty;
        g_par[PAR_BT + c * 3 + 2] = tz;
        double rc = a[ACC_RCNT + c];
        otx += rc * tx; oty += rc * ty; otz += rc * tz;
        fbx += cntd * tx; fby += cntd * ty; fbz += cntd * tz;
        tbx += (double)ty * rsz - (double)tz * rsy;
        tby += (double)tz * rsx - (double)tx * rsz;
        tbz += (double)tx * rsy - (double)ty * rsx;
    }
    double invR = 1.0 / (double)n_rec;
    double ox = (a[ACC_RSUM + 0] + otx) * invR;
    double oy = (a[ACC_RSUM + 1] + oty) * invR;
    double oz = (a[ACC_RSUM + 2] + otz) * invR;
    g_par[PAR_OR + 0] = (float)ox;
    g_par[PAR_OR + 1] = (float)oy;
    g_par[PAR_OR + 2] = (float)oz;

    double Fx = (double)k2 * (a[ACC_PRP + 0] - refx + fbx);
    double Fy = (double)k2 * (a[ACC_PRP + 1] - refy + fby);
    double Fz = (double)k2 * (a[ACC_PRP + 2] - refz + fbz);
    double Tx = -(double)k2 * (a[ACC_PCR + 0] + tbx);
    double Ty = -(double)k2 * (a[ACC_PCR + 1] + tby);
    double Tz = -(double)k2 * (a[ACC_PCR + 2] + tbz);
    Tx -= oy * Fz - oz * Fy;
    Ty -= oz * Fx - ox * Fz;
    Tz -= ox * Fy - oy * Fx;

    g_par[PAR_FM + 0] = (float)(Fx * invR);
    g_par[PAR_FM + 1] = (float)(Fy * invR);
    g_par[PAR_FM + 2] = (float)(Fz * invR);
    g_par[PAR_TM + 0] = (float)(Tx * invR);
    g_par[PAR_TM + 1] = (float)(Ty * invR);
    g_par[PAR_TM + 2] = (float)(Tz * invR);
}

// Pass C: coalesced output over ALL atoms, 4 atoms/thread, interleaved
// assignment; g_par staged in shared once per block.
#define OTPB 256
#define APT  4
#define TILE (OTPB * APT)
__global__ void k_out(const float* __restrict__ pos,
                      float* __restrict__ out, int n_atoms, int base) {
    __shared__ float sp[TILE * 3];
    __shared__ float so[TILE * 3];
    __shared__ float par[PAR_N];
    if (threadIdx.x < PAR_N) par[threadIdx.x] = g_par[threadIdx.x];

    long long a0 = (long long)blockIdx.x * TILE;
    bool full = (a0 + TILE <= (long long)n_atoms);

    if (full) {
        const float4* src = (const float4*)(pos + 3 * a0);
#pragma unroll
        for (int m = 0; m < 3; ++m)
            ((float4*)sp)[threadIdx.x + m * OTPB] = src[threadIdx.x + m * OTPB];
    } else {
        long long nfl = ((long long)n_atoms - a0) * 3;
        for (int t = threadIdx.x; t < nfl; t += OTPB)
            sp[t] = pos[3 * a0 + t];
    }
    __syncthreads();

    float fm0 = par[PAR_FM + 0], fm1 = par[PAR_FM + 1], fm2 = par[PAR_FM + 2];
    float tm0 = par[PAR_TM + 0], tm1 = par[PAR_TM + 1], tm2 = par[PAR_TM + 2];
    float or0 = par[PAR_OR + 0], or1 = par[PAR_OR + 1], or2 = par[PAR_OR + 2];

#pragma unroll
    for (int m = 0; m < APT; ++m) {
        int l = threadIdx.x + m * OTPB;
        long long a = a0 + l;
        float fx = 0.f, fy = 0.f, fz = 0.f;
        if (a < n_atoms) {
            int ch = g_chain[a];
            if (ch > 0) {
                int c = ch - 1;
                float cx = sp[3 * l + 0] + par[PAR_BT + c * 3 + 0] - or0;
                float cy = sp[3 * l + 1] + par[PAR_BT + c * 3 + 1] - or1;
                float cz = sp[3 * l + 2] + par[PAR_BT + c * 3 + 2] - or2;
                float inv = 1.f / (cx * cx + cy * cy + cz * cz);
                fx = fm0 + (tm1 * cz - tm2 * cy) * inv;
                fy = fm1 + (tm2 * cx - tm0 * cz) * inv;
                fz = fm2 + (tm0 * cy - tm1 * cx) * inv;
            }
        }
        so[3 * l + 0] = fx;
        so[3 * l + 1] = fy;
        so[3 * l + 2] = fz;
    }
    __syncthreads();

    if (full && ((base & 3) == 0)) {
        float4* dst = (float4*)(out + base + 3 * a0);
#pragma unroll
        for (int m = 0; m < 3; ++m)
            dst[threadIdx.x + m * OTPB] = ((const float4*)so)[threadIdx.x + m * OTPB];
    } else {
        long long nfl = ((long long)n_atoms - a0) * 3;
        if (nfl > (long long)TILE * 3) nfl = (long long)TILE * 3;
        for (int t = threadIdx.x; t < nfl; t += OTPB)
            out[(long long)base + 3 * a0 + t] = so[t];
    }
}

extern "C" void kernel_launch(void* const* d_in, const int* in_sizes, int n_in,
                              void* d_out, int out_size) {
    const float* positions = (const float*)d_in[0];
    const float* box       = (const float*)d_in[1];
    const float* ref_poc   = (const float*)d_in[2];
    const float* kptr      = (const float*)d_in[3];
    const int*   rec_idx   = (const int*)d_in[4];
    const int*   poc_idx   = (const int*)d_in[5];
    const int*   cid       = (const int*)d_in[6];
    const int*   pcid      = (const int*)d_in[7];

    int n_atoms = in_sizes[0] / 3;
    int n_rec   = in_sizes[4];
    int n_poc   = in_sizes[5];
    int base = out_size - 3 * n_atoms;
    if (base < 0) base = 0;

    const int TPB = 256;
    int blkA = ((n_rec + 1) / 2 + TPB - 1) / TPB; if (blkA > 592) blkA = 592;
    int blkB = ((n_poc + 1) / 2 + TPB - 1) / TPB; if (blkB > 592) blkB = 592;

    if (base > 0)  // zero any leading energy slot
        cudaMemsetAsync(d_out, 0, (size_t)base * sizeof(float));
    k_ab<<<blkA + blkB, TPB>>>(positions, rec_idx, cid, ref_poc, poc_idx, pcid,
                               n_rec, n_poc, blkA, blkB);
    k_setup<<<1, 128>>>(box, kptr, n_rec);
    k_out<<<(n_atoms + TILE - 1) / TILE, OTPB>>>(positions, (float*)d_out, n_atoms, base);
}